// round 4
// baseline (speedup 1.0000x reference)
#include <cuda_runtime.h>

#define NB 32
#define NA 286
#define CI 23
#define HH 100
#define KP 112          // k padded to 112 (8B/16B-friendly, zeros in pad)
#define NPAIR 56        // KP/2 packed pairs
#define TA 32
#define NSPLIT 2

typedef unsigned long long ull;

__device__ float g_W[NB * NA * KP];      // 0.5 * (features @ rW2^T), padded
__device__ float g_c[NB * NA];           // rb2 . features
__device__ float g_part[NSPLIT][NB * NA];

// ---- packed f32x2 helpers ----
__device__ __forceinline__ ull pk2(float x, float y) {
    ull r; asm("mov.b64 %0, {%1,%2};" : "=l"(r) : "f"(x), "f"(y)); return r;
}
__device__ __forceinline__ void unpk2(float& x, float& y, ull v) {
    asm("mov.b64 {%0,%1}, %2;" : "=f"(x), "=f"(y) : "l"(v));
}
__device__ __forceinline__ ull fma2(ull a, ull b, ull c) {
    ull d; asm("fma.rn.f32x2 %0, %1, %2, %3;" : "=l"(d) : "l"(a), "l"(b), "l"(c)); return d;
}
__device__ __forceinline__ ull add2(ull a, ull b) {
    ull d; asm("add.rn.f32x2 %0, %1, %2;" : "=l"(d) : "l"(a), "l"(b)); return d;
}

// ---------------------------------------------------------------------------
// Kernel A: warp per (z,b) row.
//   g_W[row, k] = 0.5 * sum_c rW2[k,c]*f[c]   (k<100; zeros for 100<=k<112)
//   g_c[row]    = rb2 . f
// ---------------------------------------------------------------------------
__global__ __launch_bounds__(256) void kA(const float* __restrict__ feat,
                                          const float* __restrict__ rW2,
                                          const float* __restrict__ rb2) {
    __shared__ float s_w2[HH * CI];     // 9.2 KB
    __shared__ float s_f[8][24];
    int t = threadIdx.x;
    for (int i = t; i < HH * CI; i += 256) s_w2[i] = rW2[i];

    int w = t >> 5, lane = t & 31;
    int row = blockIdx.x * 8 + w;
    bool rv = (row < NB * NA);
    if (rv && lane < CI) s_f[w][lane] = feat[row * CI + lane];
    __syncthreads();
    if (!rv) return;

    int k0 = lane, k1 = lane + 32, k2 = lane + 64, k3 = lane + 96;
    float a0 = 0.f, a1 = 0.f, a2 = 0.f, a3 = 0.f;
#pragma unroll
    for (int c = 0; c < CI; c++) {
        float fv = s_f[w][c];
        a0 = fmaf(fv, s_w2[k0 * CI + c], a0);
        a1 = fmaf(fv, s_w2[k1 * CI + c], a1);
        a2 = fmaf(fv, s_w2[k2 * CI + c], a2);
        if (k3 < HH) a3 = fmaf(fv, s_w2[k3 * CI + c], a3);
    }
    float* Wr = g_W + (size_t)row * KP;
    Wr[k0] = 0.5f * a0;
    Wr[k1] = 0.5f * a1;
    Wr[k2] = 0.5f * a2;
    if (k3 < KP) Wr[k3] = (k3 < HH) ? 0.5f * a3 : 0.f;

    if (lane == 0) {
        float cc = 0.f;
#pragma unroll
        for (int c = 0; c < CI; c++) cc = fmaf(rb2[c], s_f[w][c], cc);
        g_c[row] = cc;
    }
}

// ---------------------------------------------------------------------------
// Kernel B: block = (atile, z, split). 256 thr = 32 a-lanes x 8 b-lanes.
// b warp-uniform -> broadcast W/geom loads. Packed f32x2 inner loop.
// relu(t).W = (t+|t|).(0.5W)  (W pre-scaled)
// ---------------------------------------------------------------------------
__global__ __launch_bounds__(256, 4) void kB(const float* __restrict__ geom,
                                             const float* __restrict__ rW1,
                                             const float* __restrict__ rb1) {
    __shared__ __align__(16) ull s_cw[4 * NPAIR];   // per pair p: {w0p, w1p, w2p, biasp}
    __shared__ float s_red[8 * TA];

    int t = threadIdx.x;
    // build packed coefficient table (zero pad for k >= 100)
    for (int p = t; p < NPAIR; p += 256) {
        int k = 2 * p;
        float a0 = (k < HH) ? rW1[k] : 0.f;
        float a1 = (k + 1 < HH) ? rW1[k + 1] : 0.f;
        float b0 = (k < HH) ? rW1[HH + k] : 0.f;
        float b1 = (k + 1 < HH) ? rW1[HH + k + 1] : 0.f;
        float c0 = (k < HH) ? rW1[2 * HH + k] : 0.f;
        float c1 = (k + 1 < HH) ? rW1[2 * HH + k + 1] : 0.f;
        float d0 = (k < HH) ? rb1[k] : 0.f;
        float d1 = (k + 1 < HH) ? rb1[k + 1] : 0.f;
        s_cw[4 * p + 0] = pk2(a0, a1);
        s_cw[4 * p + 1] = pk2(b0, b1);
        s_cw[4 * p + 2] = pk2(c0, c1);
        s_cw[4 * p + 3] = pk2(d0, d1);
    }
    __syncthreads();

    int al = t & 31;
    int bl = t >> 5;
    int z = blockIdx.y;
    int atile = blockIdx.x;
    int sp = blockIdx.z;

    int a = atile * TA + al;
    bool valid = (a < NA);
    int ca = valid ? a : (NA - 1);

    const float* gp = geom + (size_t)z * NA * 3;
    float gax = gp[ca * 3 + 0];
    float gay = gp[ca * 3 + 1];
    float gaz = gp[ca * 3 + 2];

    const float* Wz = g_W + (size_t)z * NA * KP;
    const float* cz = g_c + (size_t)z * NA;

    const float inv_step = 1.0f / 1.5f;
    const float PIO2 = 1.57079632679489662f;
    const ull ABSM = 0x7FFFFFFF7FFFFFFFull;

    ull acc0 = 0ull, acc1 = 0ull;
    float scsum = 0.f;

    for (int b = sp * 8 + bl; b < NA; b += 8 * NSPLIT) {
        float dx = gax - gp[b * 3 + 0];
        float dy = gay - gp[b * 3 + 1];
        float dz = gaz - gp[b * 3 + 2];
        float d2 = fmaf(dx, dx, fmaf(dy, dy, fmaf(dz, dz, 1e-12f)));
        float r = d2 * rsqrtf(d2);
        float u0 = __cosf(PIO2 * fminf(fmaxf(r * inv_step, -1.f), 1.f));
        float u1 = __cosf(PIO2 * fminf(fmaxf((r - 1.5f) * inv_step, -1.f), 1.f));
        float u2 = __cosf(PIO2 * fminf(fmaxf((r - 3.0f) * inv_step, -1.f), 1.f));
        ull u0p = pk2(u0, u0), u1p = pk2(u1, u1), u2p = pk2(u2, u2);

        scsum += cz[b];

        const ulonglong2* __restrict__ Wrow =
            reinterpret_cast<const ulonglong2*>(Wz + (size_t)b * KP);
#pragma unroll 4
        for (int q = 0; q < NPAIR / 2; q++) {        // quad = 2 packed pairs = 4 k's
            ulonglong2 wv = Wrow[q];
            const ulonglong2* cw = reinterpret_cast<const ulonglong2*>(&s_cw[8 * q]);
            ulonglong2 cA = cw[0];  // {w0p, w1p} of pair 2q
            ulonglong2 cB = cw[1];  // {w2p, bp}  of pair 2q
            ulonglong2 cC = cw[2];  // pair 2q+1
            ulonglong2 cD = cw[3];

            ull t0 = fma2(u0p, cA.x, fma2(u1p, cA.y, fma2(u2p, cB.x, cB.y)));
            t0 = add2(t0, t0 & ABSM);               // t + |t|  (= 2*relu(t))
            acc0 = fma2(t0, wv.x, acc0);

            ull t1 = fma2(u0p, cC.x, fma2(u1p, cC.y, fma2(u2p, cD.x, cD.y)));
            t1 = add2(t1, t1 & ABSM);
            acc1 = fma2(t1, wv.y, acc1);
        }
    }

    float x0, x1, y0, y1;
    unpk2(x0, x1, acc0);
    unpk2(y0, y1, acc1);
    s_red[t] = (x0 + x1) + (y0 + y1) + scsum;
    __syncthreads();

    if (t < TA && valid) {
        float s = 0.f;
#pragma unroll
        for (int l = 0; l < 8; l++) s += s_red[l * TA + t];
        const float SCALE = 0.28209479177387814f / 16.911534525287763f;  // Y0/sqrt(N)
        g_part[sp][(size_t)z * NA + a] = s * SCALE;
    }
}

// ---------------------------------------------------------------------------
// Kernel C: sum split partials, then MLP head 286 -> 30 -> 10 -> 1
// ---------------------------------------------------------------------------
__global__ __launch_bounds__(32) void kC(const float* __restrict__ fc1W,
                                         const float* __restrict__ fc1b,
                                         const float* __restrict__ fc2W,
                                         const float* __restrict__ fc2b,
                                         const float* __restrict__ fc3W,
                                         const float* __restrict__ fc3b,
                                         float* __restrict__ out) {
    int z = blockIdx.x;
    int t = threadIdx.x;
    __shared__ float s1[30], s2[10];

    const float* p0 = g_part[0] + (size_t)z * NA;
    const float* p1 = g_part[1] + (size_t)z * NA;
    if (t < 30) {
        float acc = fc1b[t];
#pragma unroll 4
        for (int i = 0; i < NA; i++)
            acc = fmaf(p0[i] + p1[i], fc1W[i * 30 + t], acc);
        s1[t] = fmaxf(acc, 0.f);
    }
    __syncthreads();
    if (t < 10) {
        float acc = fc2b[t];
#pragma unroll
        for (int i = 0; i < 30; i++)
            acc = fmaf(s1[i], fc2W[i * 10 + t], acc);
        s2[t] = fmaxf(acc, 0.f);
    }
    __syncthreads();
    if (t == 0) {
        float acc = fc3b[0];
#pragma unroll
        for (int i = 0; i < 10; i++)
            acc = fmaf(s2[i], fc3W[i], acc);
        out[z] = acc;
    }
}

// ---------------------------------------------------------------------------
extern "C" void kernel_launch(void* const* d_in, const int* in_sizes, int n_in,
                              void* d_out, int out_size) {
    const float* features = (const float*)d_in[1];
    const float* geometry = (const float*)d_in[2];
    const float* rW1  = (const float*)d_in[3];
    const float* rb1  = (const float*)d_in[4];
    const float* rW2  = (const float*)d_in[5];
    const float* rb2  = (const float*)d_in[6];
    const float* fc1W = (const float*)d_in[7];
    const float* fc1b = (const float*)d_in[8];
    const float* fc2W = (const float*)d_in[9];
    const float* fc2b = (const float*)d_in[10];
    const float* fc3W = (const float*)d_in[11];
    const float* fc3b = (const float*)d_in[12];
    float* out = (float*)d_out;

    kA<<<(NB * NA + 7) / 8, 256>>>(features, rW2, rb2);
    dim3 gB((NA + TA - 1) / TA, NB, NSPLIT);
    kB<<<gB, 256>>>(geometry, rW1, rb1);
    kC<<<NB, 32>>>(fc1W, fc1b, fc2W, fc2b, fc3W, fc3b, out);
}

// round 5
// speedup vs baseline: 1.3717x; 1.3717x over previous
#include <cuda_runtime.h>

#define NB 32
#define NA 286
#define NAPB 288       // padded b (zero W rows 286..287)
#define CI 23
#define HH 100
#define KP 104         // padded k: 13 groups of 8
#define NG 13
#define BPW 36         // b's per warp (288/8)
#define CH 9           // basis chunk per warp (4 chunks)

typedef unsigned long long ull;

__device__ __align__(16) float g_W[NB * NAPB * KP];  // 0.5*(feat@rW2^T), padded
__device__ float g_c[NB * NA];
__device__ float g_part[NB * NA];
__device__ __align__(16) ull g_T[52 * 4];            // per k-pair q: {c0p,c1p,c2p,cbp}

__device__ __forceinline__ ull pk2(float x, float y) {
    ull r; asm("mov.b64 %0, {%1,%2};" : "=l"(r) : "f"(x), "f"(y)); return r;
}
__device__ __forceinline__ ull dup2(float x) {
    ull r; asm("mov.b64 %0, {%1,%1};" : "=l"(r) : "f"(x)); return r;
}
__device__ __forceinline__ void unpk2(float& x, float& y, ull v) {
    asm("mov.b64 {%0,%1}, %2;" : "=f"(x), "=f"(y) : "l"(v));
}
__device__ __forceinline__ ull fma2(ull a, ull b, ull c) {
    ull d; asm("fma.rn.f32x2 %0, %1, %2, %3;" : "=l"(d) : "l"(a), "l"(b), "l"(c)); return d;
}
__device__ __forceinline__ ull add2(ull a, ull b) {
    ull d; asm("add.rn.f32x2 %0, %1, %2;" : "=l"(d) : "l"(a), "l"(b)); return d;
}

// ---------------------------------------------------------------------------
// kA: g_W rows (0.5-scaled, zero-padded), g_c, and coefficient table g_T.
// 288 blocks x 256 thr; block = (z = bx/9, 32 rows); warp handles 4 rows.
// ---------------------------------------------------------------------------
__global__ __launch_bounds__(256) void kA(const float* __restrict__ feat,
                                          const float* __restrict__ rW1,
                                          const float* __restrict__ rb1,
                                          const float* __restrict__ rW2,
                                          const float* __restrict__ rb2) {
    __shared__ float s_w2[HH * CI];
    __shared__ float s_f[8][4][24];
    int t = threadIdx.x, w = t >> 5, lane = t & 31;
    int bx = blockIdx.x;

    if (bx == 0 && t < 52) {             // packed coefficient table, k-pad zeroed
        int k = 2 * t;
        float a0 = (k < HH) ? rW1[k] : 0.f;
        float a1 = (k + 1 < HH) ? rW1[k + 1] : 0.f;
        float b0 = (k < HH) ? rW1[HH + k] : 0.f;
        float b1 = (k + 1 < HH) ? rW1[HH + k + 1] : 0.f;
        float c0 = (k < HH) ? rW1[2 * HH + k] : 0.f;
        float c1 = (k + 1 < HH) ? rW1[2 * HH + k + 1] : 0.f;
        float d0 = (k < HH) ? rb1[k] : 0.f;
        float d1 = (k + 1 < HH) ? rb1[k + 1] : 0.f;
        g_T[t * 4 + 0] = pk2(a0, a1);
        g_T[t * 4 + 1] = pk2(b0, b1);
        g_T[t * 4 + 2] = pk2(c0, c1);
        g_T[t * 4 + 3] = pk2(d0, d1);
    }

    for (int i = t; i < HH * CI; i += 256) s_w2[i] = rW2[i];

    int z = bx / 9;
    int jb = (bx % 9) * 32 + w * 4;
    for (int i = 0; i < 4; i++) {
        int j = jb + i;
        if (j < NA && lane < CI) s_f[w][i][lane] = feat[(z * NA + j) * CI + lane];
    }
    __syncthreads();

    for (int i = 0; i < 4; i++) {
        int j = jb + i;
        float* Wr = g_W + (size_t)(z * NAPB + j) * KP;
        int k0 = lane, k1 = lane + 32, k2 = lane + 64, k3 = lane + 96;
        if (j < NA) {
            float a0 = 0.f, a1 = 0.f, a2 = 0.f, a3 = 0.f;
#pragma unroll
            for (int c = 0; c < CI; c++) {
                float fv = s_f[w][i][c];
                a0 = fmaf(fv, s_w2[k0 * CI + c], a0);
                a1 = fmaf(fv, s_w2[k1 * CI + c], a1);
                a2 = fmaf(fv, s_w2[k2 * CI + c], a2);
                if (k3 < HH) a3 = fmaf(fv, s_w2[k3 * CI + c], a3);
            }
            Wr[k0] = 0.5f * a0;
            Wr[k1] = 0.5f * a1;
            Wr[k2] = 0.5f * a2;
            if (k3 < KP) Wr[k3] = (k3 < HH) ? 0.5f * a3 : 0.f;
            if (lane == 0) {
                float cc = 0.f;
#pragma unroll
                for (int c = 0; c < CI; c++) cc = fmaf(rb2[c], s_f[w][i][c], cc);
                g_c[z * NA + j] = cc;
            }
        } else {
            Wr[k0] = 0.f; Wr[k1] = 0.f; Wr[k2] = 0.f;
            if (k3 < KP) Wr[k3] = 0.f;
        }
    }
}

// ---------------------------------------------------------------------------
// kB: block = (atile, z); 256 thr = 32 a-lanes x 8 b-warps.
// Warp owns b in [bl*36, bl*36+36), 4 chunks of 9. Basis in regs, coeffs in
// regs (uniform LDG), W via uniform LDG.128. NO smem in the hot loop.
// ---------------------------------------------------------------------------
__global__ __launch_bounds__(256, 2) void kB(const float* __restrict__ geom) {
    __shared__ float s_red[256];
    int t = threadIdx.x, al = t & 31, bl = t >> 5;
    int z = blockIdx.y, atile = blockIdx.x;
    int a = atile * 32 + al;
    bool valid = (a < NA);
    int ca = valid ? a : (NA - 1);

    const float* gp = geom + (size_t)z * NA * 3;
    float gax = gp[ca * 3 + 0];
    float gay = gp[ca * 3 + 1];
    float gaz = gp[ca * 3 + 2];

    const float* Wz = g_W + (size_t)z * NAPB * KP;
    const ulonglong2* T2 = (const ulonglong2*)g_T;

    const float INV = 1.0f / 1.5f;
    const float PIO2 = 1.57079632679489662f;
    const ull ABSM = 0x7FFFFFFF7FFFFFFFull;

    ull acc0 = 0ull, acc1 = 0ull;

    for (int c0 = 0; c0 < BPW; c0 += CH) {
        int bb = bl * BPW + c0;
        float x0[CH], x1[CH], x2[CH];
#pragma unroll
        for (int i = 0; i < CH; i++) {
            int b = bb + i;
            int bc = (b < NA) ? b : (NA - 1);
            float dx = gax - gp[bc * 3 + 0];
            float dy = gay - gp[bc * 3 + 1];
            float dz = gaz - gp[bc * 3 + 2];
            float d2 = fmaf(dx, dx, fmaf(dy, dy, fmaf(dz, dz, 1e-12f)));
            float r = d2 * rsqrtf(d2);
            bool s = (r >= 1.5f);
            float rr = s ? (r - 1.5f) : r;
            float ulo = __cosf(PIO2 * fminf(rr * INV, 1.f));
            float uhi = __cosf(PIO2 * fminf(rr * INV - 1.f, 1.f));
            x0[i] = s ? 0.f : ulo;
            x1[i] = s ? ulo : uhi;
            x2[i] = s ? uhi : 0.f;
        }
#pragma unroll 1
        for (int g = 0; g < NG; g++) {
            ulonglong2 A0 = T2[g * 8 + 0], B0 = T2[g * 8 + 1];
            ulonglong2 A1 = T2[g * 8 + 2], B1 = T2[g * 8 + 3];
            ulonglong2 A2 = T2[g * 8 + 4], B2 = T2[g * 8 + 5];
            ulonglong2 A3 = T2[g * 8 + 6], B3 = T2[g * 8 + 7];
            const float* Wp = Wz + (size_t)bb * KP + g * 8;
#pragma unroll
            for (int i = 0; i < CH; i++) {
                const ulonglong2* wr = (const ulonglong2*)(Wp + i * KP);
                ulonglong2 wlo = wr[0];   // k-pairs 0,1 of this group
                ulonglong2 whi = wr[1];   // k-pairs 2,3
                ull x0p = dup2(x0[i]), x1p = dup2(x1[i]), x2p = dup2(x2[i]);

                ull t0 = fma2(x0p, A0.x, fma2(x1p, A0.y, fma2(x2p, B0.x, B0.y)));
                t0 = add2(t0, t0 & ABSM);
                acc0 = fma2(t0, wlo.x, acc0);

                ull t1 = fma2(x0p, A1.x, fma2(x1p, A1.y, fma2(x2p, B1.x, B1.y)));
                t1 = add2(t1, t1 & ABSM);
                acc1 = fma2(t1, wlo.y, acc1);

                ull t2 = fma2(x0p, A2.x, fma2(x1p, A2.y, fma2(x2p, B2.x, B2.y)));
                t2 = add2(t2, t2 & ABSM);
                acc0 = fma2(t2, whi.x, acc0);

                ull t3 = fma2(x0p, A3.x, fma2(x1p, A3.y, fma2(x2p, B3.x, B3.y)));
                t3 = add2(t3, t3 & ABSM);
                acc1 = fma2(t3, whi.y, acc1);
            }
        }
    }

    float p0, p1, q0, q1;
    unpk2(p0, p1, acc0);
    unpk2(q0, q1, acc1);
    s_red[t] = (p0 + p1) + (q0 + q1);
    __syncthreads();

    if (t < 32 && valid) {
        float s = 0.f;
#pragma unroll
        for (int l = 0; l < 8; l++) s += s_red[l * 32 + t];
        const float SCALE = 0.28209479177387814f / 16.911534525287763f;  // Y0/sqrt(N)
        g_part[(size_t)z * NA + a] = s * SCALE;
    }
}

// ---------------------------------------------------------------------------
// kC: csum = SCALE * sum_b c[z,b]; then MLP head 286 -> 30 -> 10 -> 1
// ---------------------------------------------------------------------------
__global__ __launch_bounds__(32) void kC(const float* __restrict__ fc1W,
                                         const float* __restrict__ fc1b,
                                         const float* __restrict__ fc2W,
                                         const float* __restrict__ fc2b,
                                         const float* __restrict__ fc3W,
                                         const float* __restrict__ fc3b,
                                         float* __restrict__ out) {
    int z = blockIdx.x, t = threadIdx.x;
    __shared__ float s1[30], s2[10];

    float cs = 0.f;
    for (int i = t; i < NA; i += 32) cs += g_c[z * NA + i];
#pragma unroll
    for (int o = 16; o > 0; o >>= 1) cs += __shfl_xor_sync(0xffffffffu, cs, o);
    const float SCALE = 0.28209479177387814f / 16.911534525287763f;
    cs *= SCALE;

    const float* p = g_part + (size_t)z * NA;
    if (t < 30) {
        float acc = fc1b[t];
#pragma unroll 4
        for (int i = 0; i < NA; i++)
            acc = fmaf(p[i] + cs, fc1W[i * 30 + t], acc);
        s1[t] = fmaxf(acc, 0.f);
    }
    __syncthreads();
    if (t < 10) {
        float acc = fc2b[t];
#pragma unroll
        for (int i = 0; i < 30; i++)
            acc = fmaf(s1[i], fc2W[i * 10 + t], acc);
        s2[t] = fmaxf(acc, 0.f);
    }
    __syncthreads();
    if (t == 0) {
        float acc = fc3b[0];
#pragma unroll
        for (int i = 0; i < 10; i++)
            acc = fmaf(s2[i], fc3W[i], acc);
        out[z] = acc;
    }
}

// ---------------------------------------------------------------------------
extern "C" void kernel_launch(void* const* d_in, const int* in_sizes, int n_in,
                              void* d_out, int out_size) {
    const float* features = (const float*)d_in[1];
    const float* geometry = (const float*)d_in[2];
    const float* rW1  = (const float*)d_in[3];
    const float* rb1  = (const float*)d_in[4];
    const float* rW2  = (const float*)d_in[5];
    const float* rb2  = (const float*)d_in[6];
    const float* fc1W = (const float*)d_in[7];
    const float* fc1b = (const float*)d_in[8];
    const float* fc2W = (const float*)d_in[9];
    const float* fc2b = (const float*)d_in[10];
    const float* fc3W = (const float*)d_in[11];
    const float* fc3b = (const float*)d_in[12];
    float* out = (float*)d_out;

    kA<<<288, 256>>>(features, rW1, rb1, rW2, rb2);
    dim3 gB(9, NB);
    kB<<<gB, 256>>>(geometry);
    kC<<<NB, 32>>>(fc1W, fc1b, fc2W, fc2b, fc3W, fc3b, out);
}